// round 4
// baseline (speedup 1.0000x reference)
#include <cuda_runtime.h>
#include <cuda_bf16.h>
#include <cstdint>
#include <math.h>

#define B_ROWS 4096
#define N_ROWS 8192
#define D_DIM  256
#define TILE_BYTES 65536     // 128 rows x 256 bf16 (pre-swizzled)
#define SUBK_BYTES 16384     // 128 rows x 64 bf16 sub-tile
#define IDESC_F16 0x8200490u // f32 acc, bf16 a/b, M=128, N=128

// ---- smem layout (dynamic) ----
#define SMEM_A    0
#define SMEM_B0   65536
#define SMEM_B1   131072
#define SMEM_CTRL 196608             // tmem ptr (4B)
#define SMEM_MBAR (SMEM_CTRL + 16)   // 8 barriers x 8B
#define SMEM_SRED (SMEM_CTRL + 128)  // 256 floats
#define SMEM_TOTAL (SMEM_CTRL + 128 + 1024)

// barriers: [0]=b_full0 [1]=b_full1 [2]=b_free0 [3]=b_free1
//           [4]=d_full0 [5]=d_full1 [6]=d_free0 [7]=d_free1
#define BAR(i) (smem_base + SMEM_MBAR + 8 * (i))

// Arch-specific gate: tcgen05 is an 'a'-feature. The harness's extra
// compute_103 (family-portable) gencode pass must see NO tcgen05 PTX.
#if defined(__CUDA_ARCH__) && \
    (defined(__CUDA_ARCH_FEAT_SM103_ALL) || \
     (defined(__CUDA_ARCH_SPECIFIC__) && (__CUDA_ARCH_SPECIFIC__ == 1030)))
#define TC_ENABLED 1
#else
#define TC_ENABLED 0
#endif

// ---- device globals (no allocation allowed) ----
__device__ __align__(16) unsigned char g_zswz[N_ROWS * D_DIM * 2]; // 4MB bf16, pre-swizzled
__device__ float g_ps[2][N_ROWS];
__device__ float g_posd[N_ROWS];

// ---------------- arch-neutral PTX helpers (sm_90 baseline) ----------------
__device__ __forceinline__ uint32_t smem_u32(const void* p) {
    uint32_t a;
    asm("{ .reg .u64 t; cvta.to.shared.u64 t, %1; cvt.u32.u64 %0, t; }" : "=r"(a) : "l"(p));
    return a;
}
#define MBARRIER_INIT(addr, cnt) \
    asm volatile("mbarrier.init.shared.b64 [%0], %1;" :: "r"(addr), "r"((uint32_t)(cnt)) : "memory")
#define MBARRIER_EXPECT_TX(addr, bytes) \
    asm volatile("mbarrier.arrive.expect_tx.shared.b64 _, [%0], %1;" :: "r"(addr), "r"((uint32_t)(bytes)) : "memory")
#define MBARRIER_ARRIVE(addr) \
    asm volatile("mbarrier.arrive.shared.b64 _, [%0];" :: "r"(addr) : "memory")
#define MBARRIER_WAIT_PARITY(addr, par) do {                                   \
    uint32_t _m = (addr), _p = (uint32_t)(par), _done;                          \
    asm volatile("{\n\t.reg .pred p;\n\t"                                       \
        "mbarrier.try_wait.parity.acquire.cta.shared::cta.b64 p, [%1], %2;\n\t" \
        "selp.b32 %0, 1, 0, p;\n\t}" : "=r"(_done) : "r"(_m), "r"(_p) : "memory"); \
    if (!_done) {                                                               \
        asm volatile("{\n\t.reg .pred P1;\n\t"                                  \
            "WL_%=:\n\t"                                                        \
            "mbarrier.try_wait.parity.acquire.cta.shared::cta.b64 P1, [%0], %1, 0x989680;\n\t" \
            "@P1 bra.uni WD_%=;\n\t"                                            \
            "bra.uni WL_%=;\n\t"                                                \
            "WD_%=:\n\t}" :: "r"(_m), "r"(_p) : "memory");                      \
    } } while (0)
#define FENCE_PROXY_ASYNC() asm volatile("fence.proxy.async.shared::cta;" ::: "memory")

__device__ __forceinline__ void bulk_copy(uint32_t dst_smem, const void* src, uint32_t bytes, uint32_t mbar) {
    asm volatile("cp.async.bulk.shared::cluster.global.mbarrier::complete_tx::bytes [%0], [%1], %2, [%3];"
        :: "r"(dst_smem), "l"(src), "r"(bytes), "r"(mbar) : "memory");
}
__device__ __forceinline__ float fast_ex2(float x) {
    float y; asm("ex2.approx.f32 %0, %1;" : "=f"(y) : "f"(x)); return y;
}
__device__ __forceinline__ uint32_t swz128(uint32_t x) { return x ^ ((x >> 3) & 0x70); }

// ---------------- tcgen05 helpers (sm_103a only) ----------------
#if TC_ENABLED
#define TCGEN05_ALLOC(sm, n) \
    asm volatile("tcgen05.alloc.cta_group::1.sync.aligned.shared::cta.b32 [%0], %1;" :: "r"(sm), "r"((uint32_t)(n)) : "memory")
#define TCGEN05_DEALLOC(t, n) \
    asm volatile("tcgen05.dealloc.cta_group::1.sync.aligned.b32 %0, %1;" :: "r"(t), "r"((uint32_t)(n)))
#define TCGEN05_RELINQ() \
    asm volatile("tcgen05.relinquish_alloc_permit.cta_group::1.sync.aligned;")
#define TCGEN05_COMMIT(mb) \
    asm volatile("tcgen05.commit.cta_group::1.mbarrier::arrive::one.shared::cluster.b64 [%0];" :: "r"(mb) : "memory")
#define TCGEN05_WAIT_LD()  asm volatile("tcgen05.wait::ld.sync.aligned;" ::: "memory")
#define TCGEN05_FENCE_BEFORE() asm volatile("tcgen05.fence::before_thread_sync;" ::: "memory")
#define TCGEN05_FENCE_AFTER()  asm volatile("tcgen05.fence::after_thread_sync;" ::: "memory")

#define TCGEN05_LD_X16(r, a) \
    asm volatile("tcgen05.ld.sync.aligned.32x32b.x16.b32 " \
        "{%0,%1,%2,%3,%4,%5,%6,%7,%8,%9,%10,%11,%12,%13,%14,%15}, [%16];" \
        : "=r"((r)[0]),"=r"((r)[1]),"=r"((r)[2]),"=r"((r)[3]),"=r"((r)[4]),"=r"((r)[5]),"=r"((r)[6]),"=r"((r)[7]), \
          "=r"((r)[8]),"=r"((r)[9]),"=r"((r)[10]),"=r"((r)[11]),"=r"((r)[12]),"=r"((r)[13]),"=r"((r)[14]),"=r"((r)[15]) \
        : "r"(a))

// SW128 descriptor: layout=2 (SW128), version=1, SBO=64, LBO=1
__device__ __forceinline__ uint64_t make_desc(uint32_t addr) {
    uint64_t base = (uint64_t(2) << 61) | (uint64_t(1) << 46) | (uint64_t(64) << 32) | (uint64_t(1) << 16);
    return base | ((uint64_t)(addr >> 4) & 0x3FFF);
}
__device__ __forceinline__ void mma_f16_ss(uint32_t d, uint64_t ad, uint64_t bd, uint32_t idesc, bool en) {
    uint32_t e = en ? 1u : 0u;
    asm volatile("{\n\t.reg .pred p;\n\tsetp.ne.u32 p, %5, 0;\n\t"
        "tcgen05.mma.cta_group::1.kind::f16 [%0], %1, %2, %3, {%4,%4,%4,%4}, p;\n\t}"
        :: "r"(d), "l"(ad), "l"(bd), "r"(idesc), "r"(0u), "r"(e) : "memory");
}

// process 16 TMEM values: e = exp2(2*log2e*(d-1)); accumulate into 4 lanes
// MODE: 0 = plain, 1 = diagonal tile (mask j==i), 2 = positive tile (capture d)
template<int MODE>
__device__ __forceinline__ void proc16(const uint32_t* dv, int cb, int rrow, int gi,
                                       float& a0, float& a1, float& a2, float& a3) {
    const float C1 = 2.8853900817779268f;   // 2*log2(e)
    #pragma unroll
    for (int k = 0; k < 16; ++k) {
        float d = __uint_as_float(dv[k]);
        float e = fast_ex2(fmaf(d, C1, -C1));
        if (MODE == 1) { if (cb + k == rrow) e = 0.f; }
        if (MODE == 2) { if (cb + k == rrow) g_posd[gi] = d; }
        if ((k & 3) == 0) a0 += e; else if ((k & 3) == 1) a1 += e;
        else if ((k & 3) == 2) a2 += e; else a3 += e;
    }
}

// pipelined tile epilogue: LDTM chunk c+1 in flight while chunk c is processed
template<int MODE>
__device__ __forceinline__ void epi_tile(uint32_t taddr, int colbase, int rrow, int gi,
                                         uint32_t dfree_bar, int lane,
                                         float& a0, float& a1, float& a2, float& a3) {
    uint32_t dvA[16], dvB[16];
    TCGEN05_LD_X16(dvA, taddr + 0);
    TCGEN05_WAIT_LD();
    TCGEN05_LD_X16(dvB, taddr + 16);
    proc16<MODE>(dvA, colbase + 0, rrow, gi, a0, a1, a2, a3);
    TCGEN05_WAIT_LD();
    TCGEN05_LD_X16(dvA, taddr + 32);
    proc16<MODE>(dvB, colbase + 16, rrow, gi, a0, a1, a2, a3);
    TCGEN05_WAIT_LD();
    TCGEN05_LD_X16(dvB, taddr + 48);
    proc16<MODE>(dvA, colbase + 32, rrow, gi, a0, a1, a2, a3);
    TCGEN05_WAIT_LD();                        // all 4 LDTMs for this tile done
    TCGEN05_FENCE_BEFORE();
    if (lane == 0) MBARRIER_ARRIVE(dfree_bar); // free D buffer before last math
    proc16<MODE>(dvB, colbase + 48, rrow, gi, a0, a1, a2, a3);
}
#endif // TC_ENABLED

// ---------------------------------------------------------------------------
// Kernel 1: normalize rows, convert to bf16, store PRE-SWIZZLED tile layout.
// ---------------------------------------------------------------------------
__global__ void prep_kernel(const float* __restrict__ zi, const float* __restrict__ zj) {
    int warp = (blockIdx.x * blockDim.x + threadIdx.x) >> 5;
    int lane = threadIdx.x & 31;
    if (warp >= N_ROWS) return;
    const float* src = (warp < B_ROWS) ? (zi + (size_t)warp * D_DIM)
                                       : (zj + (size_t)(warp - B_ROWS) * D_DIM);
    const float4* s4 = (const float4*)src;
    float4 v0 = s4[lane * 2];
    float4 v1 = s4[lane * 2 + 1];
    float ss = v0.x*v0.x + v0.y*v0.y + v0.z*v0.z + v0.w*v0.w
             + v1.x*v1.x + v1.y*v1.y + v1.z*v1.z + v1.w*v1.w;
    #pragma unroll
    for (int o = 16; o; o >>= 1) ss += __shfl_xor_sync(0xffffffffu, ss, o);
    float inv = 1.0f / fmaxf(sqrtf(ss), 1e-12f);

    __nv_bfloat162 p0 = __floats2bfloat162_rn(v0.x*inv, v0.y*inv);
    __nv_bfloat162 p1 = __floats2bfloat162_rn(v0.z*inv, v0.w*inv);
    __nv_bfloat162 p2 = __floats2bfloat162_rn(v1.x*inv, v1.y*inv);
    __nv_bfloat162 p3 = __floats2bfloat162_rn(v1.z*inv, v1.w*inv);
    uint4 u;
    u.x = *reinterpret_cast<uint32_t*>(&p0);
    u.y = *reinterpret_cast<uint32_t*>(&p1);
    u.z = *reinterpret_cast<uint32_t*>(&p2);
    u.w = *reinterpret_cast<uint32_t*>(&p3);

    int t = warp >> 7, r = warp & 127;
    int kc = lane >> 3;                         // which K 64-chunk
    uint32_t inner = swz128((uint32_t)(r * 128 + (lane & 7) * 16));
    *reinterpret_cast<uint4*>(g_zswz + (size_t)t * TILE_BYTES + kc * SUBK_BYTES + inner) = u;
}

// ---------------------------------------------------------------------------
// Kernel 2: tcgen05 GEMM (Zn @ Zn^T) fused with fixed-max exp-sum epilogue.
// Grid 128: blockIdx = m (0..63) | h<<6 (j-half). 256 threads (8 warps).
// ---------------------------------------------------------------------------
__global__ __launch_bounds__(256, 1) void gemm_lse_kernel() {
#if TC_ENABLED
    extern __shared__ char smem[];
    const uint32_t smem_base = smem_u32(smem);
    const int tid  = threadIdx.x;
    const int wid  = tid >> 5;
    const int lane = tid & 31;
    const int m    = blockIdx.x & 63;
    const int h    = blockIdx.x >> 6;
    const int jt0  = h * 32;
    const int nt   = 32;
    const int pos_t = m ^ 32;                  // tile holding positive pairs

    // --- setup: TMEM alloc, barriers, resident A tile ---
    if (wid == 0) TCGEN05_ALLOC(smem_base + SMEM_CTRL, 256);
    if (tid == 0) {
        MBARRIER_INIT(BAR(0), 1); MBARRIER_INIT(BAR(1), 1);  // b_full (tx)
        MBARRIER_INIT(BAR(2), 1); MBARRIER_INIT(BAR(3), 1);  // b_free
        MBARRIER_INIT(BAR(4), 1); MBARRIER_INIT(BAR(5), 1);  // d_full
        MBARRIER_INIT(BAR(6), 8); MBARRIER_INIT(BAR(7), 8);  // d_free (8 warps)
    }
    {   // load A tile (pre-swizzled image, plain copy)
        const uint4* src = reinterpret_cast<const uint4*>(g_zswz + (size_t)m * TILE_BYTES);
        uint4* dst = reinterpret_cast<uint4*>(smem + SMEM_A);
        #pragma unroll
        for (int i = 0; i < 16; ++i) dst[tid + i * 256] = src[tid + i * 256];
    }
    __syncthreads();
    uint32_t tmem_base;
    asm volatile("ld.shared.b32 %0, [%1];" : "=r"(tmem_base) : "r"(smem_base + SMEM_CTRL));

    // --- prologue: load B tiles 0,1; issue MMA tile 0 ---
    if (tid == 32) {
        MBARRIER_EXPECT_TX(BAR(0), TILE_BYTES);
        bulk_copy(smem_base + SMEM_B0, g_zswz + (size_t)(jt0 + 0) * TILE_BYTES, TILE_BYTES, BAR(0));
        MBARRIER_EXPECT_TX(BAR(1), TILE_BYTES);
        bulk_copy(smem_base + SMEM_B1, g_zswz + (size_t)(jt0 + 1) * TILE_BYTES, TILE_BYTES, BAR(1));
    }
    if (tid == 0) {
        FENCE_PROXY_ASYNC();                    // A tile STS -> async proxy
        MBARRIER_WAIT_PARITY(BAR(0), 0);
        TCGEN05_FENCE_AFTER();
        #pragma unroll
        for (int kc = 0; kc < 4; ++kc)
            #pragma unroll
            for (int q = 0; q < 4; ++q)
                mma_f16_ss(tmem_base,
                           make_desc(smem_base + SMEM_A)  + kc * 1024 + q * 2,
                           make_desc(smem_base + SMEM_B0) + kc * 1024 + q * 2,
                           IDESC_F16, (kc | q) != 0);
        TCGEN05_COMMIT(BAR(4));
    }

    // --- epilogue state ---
    const int rrow   = (wid & 3) * 32 + lane;          // this thread's row in tile
    const int gi     = m * 128 + rrow;
    const int colbase = (tid >> 7) * 64;               // WG0: cols 0-63, WG1: 64-127
    float acc0 = 0.f, acc1 = 0.f, acc2 = 0.f, acc3 = 0.f;

    for (int l = 0; l < nt; ++l) {
        const int s = l & 1, r = l >> 1;
        const int jt_g = jt0 + l;

        // 1. wait D[s] full
        MBARRIER_WAIT_PARITY(BAR(4 + s), r & 1);
        TCGEN05_FENCE_AFTER();

        if (tid == 0) {
            // 2. B buf s consumed by MMA l
            MBARRIER_ARRIVE(BAR(2 + s));
            // 3. issue MMA for tile l+1 into D[s^1]
            if (l + 1 < nt) {
                const int s2 = s ^ 1, r2 = (l + 1) >> 1;
                MBARRIER_WAIT_PARITY(BAR(0 + s2), r2 & 1);
                if (l + 1 >= 2) MBARRIER_WAIT_PARITY(BAR(6 + s2), (r2 - 1) & 1);
                TCGEN05_FENCE_AFTER();
                uint32_t bbuf = smem_base + (s2 ? SMEM_B1 : SMEM_B0);
                #pragma unroll
                for (int kc = 0; kc < 4; ++kc)
                    #pragma unroll
                    for (int q = 0; q < 4; ++q)
                        mma_f16_ss(tmem_base + s2 * 128,
                                   make_desc(smem_base + SMEM_A) + kc * 1024 + q * 2,
                                   make_desc(bbuf)               + kc * 1024 + q * 2,
                                   IDESC_F16, (kc | q) != 0);
                TCGEN05_COMMIT(BAR(4 + s2));
            }
        }
        // 4. producer: load tile l+2 into B[s]
        if (tid == 32 && l + 2 < nt) {
            MBARRIER_WAIT_PARITY(BAR(2 + s), r & 1);
            MBARRIER_EXPECT_TX(BAR(0 + s), TILE_BYTES);
            bulk_copy(smem_base + (s ? SMEM_B1 : SMEM_B0),
                      g_zswz + (size_t)(jt_g + 2) * TILE_BYTES, TILE_BYTES, BAR(0 + s));
        }

        // 5+6. pipelined LDTM + exp-sum epilogue (fixed max = 2)
        const uint32_t taddr = tmem_base + s * 128 + colbase + ((uint32_t)((tid & 127) >> 5) << 21);
        if (jt_g == m) {
            epi_tile<1>(taddr, colbase, rrow, gi, BAR(6 + s), lane, acc0, acc1, acc2, acc3);
        } else if (jt_g == pos_t) {
            epi_tile<2>(taddr, colbase, rrow, gi, BAR(6 + s), lane, acc0, acc1, acc2, acc3);
        } else {
            epi_tile<0>(taddr, colbase, rrow, gi, BAR(6 + s), lane, acc0, acc1, acc2, acc3);
        }
    }

    // --- combine the two column-half partials per row, store ---
    float stot = (acc0 + acc1) + (acc2 + acc3);
    float* sred = reinterpret_cast<float*>(smem + SMEM_SRED);
    sred[(tid >> 7) * 128 + rrow] = stot;
    __syncthreads();
    if (tid < 128) g_ps[h][m * 128 + tid] = sred[tid] + sred[128 + tid];

    __syncthreads();
    if (wid == 0) { TCGEN05_RELINQ(); TCGEN05_DEALLOC(tmem_base, 256); }
#endif // TC_ENABLED
}

// ---------------------------------------------------------------------------
// Kernel 3: loss_i = 2 + log(S_i) - 2*d_pos_i ; out = mean.
// ---------------------------------------------------------------------------
__global__ void reduce_kernel(float* __restrict__ out) {
    __shared__ float sbuf[256];
    int tid = threadIdx.x;
    float s = 0.0f;
    for (int i = tid; i < N_ROWS; i += 256) {
        float S = g_ps[0][i] + g_ps[1][i];
        s += 2.0f + logf(S) - 2.0f * g_posd[i];
    }
    sbuf[tid] = s;
    __syncthreads();
    #pragma unroll
    for (int o = 128; o; o >>= 1) {
        if (tid < o) sbuf[tid] += sbuf[tid + o];
        __syncthreads();
    }
    if (tid == 0) out[0] = sbuf[0] / (float)N_ROWS;
}

// ---------------------------------------------------------------------------
extern "C" void kernel_launch(void* const* d_in, const int* in_sizes, int n_in,
                              void* d_out, int out_size) {
    const float* zi = (const float*)d_in[0];
    const float* zj = (const float*)d_in[1];
    float* out = (float*)d_out;

    cudaFuncSetAttribute(gemm_lse_kernel,
                         cudaFuncAttributeMaxDynamicSharedMemorySize, SMEM_TOTAL);

    prep_kernel<<<(N_ROWS * 32) / 256, 256>>>(zi, zj);
    gemm_lse_kernel<<<128, 256, SMEM_TOTAL>>>();
    reduce_kernel<<<1, 256>>>(out);
}

// round 5
// speedup vs baseline: 1.1237x; 1.1237x over previous
#include <cuda_runtime.h>
#include <cuda_bf16.h>
#include <cstdint>
#include <math.h>

#define B_ROWS 4096
#define N_ROWS 8192
#define D_DIM  256
#define TILE_BYTES 65536     // 128 rows x 256 bf16 (pre-swizzled)
#define SUBK_BYTES 16384     // 128 rows x 64 bf16 sub-tile
#define HALF_BYTES 32768     // 128 rows x 128 K (half tile)
#define IDESC_F16 0x8200490u // f32 acc, bf16 a/b, M=128, N=128

// ---- smem layout (dynamic) ----
#define SMEM_A    0                    // 2 A tiles, 131072 B
#define SMEM_B    131072               // 3 half-tile slots x 32768 = 98304
#define SMEM_CTRL 229376               // tmem ptr (4B)
#define SMEM_MBAR (SMEM_CTRL + 16)     // 9 barriers x 8B
#define SMEM_SRED (SMEM_CTRL + 96)     // 512 floats
#define SMEM_TOTAL (SMEM_CTRL + 96 + 2048)

// barriers: [0]=a_full  [1..3]=b_full[slot]  [4..6]=hdone[slot]  [7..8]=d_free[p]
#define BAR(i) (smem_base + SMEM_MBAR + 8 * (i))

// Arch-specific gate: tcgen05 is an 'a'-feature; the family-portable
// compute_103 gencode pass must see NO tcgen05 PTX.
#if defined(__CUDA_ARCH__) && \
    (defined(__CUDA_ARCH_FEAT_SM103_ALL) || \
     (defined(__CUDA_ARCH_SPECIFIC__) && (__CUDA_ARCH_SPECIFIC__ == 1030)))
#define TC_ENABLED 1
#else
#define TC_ENABLED 0
#endif

// ---- device globals (no allocation allowed) ----
__device__ __align__(16) unsigned char g_zswz[N_ROWS * D_DIM * 2]; // 4MB bf16, pre-swizzled
__device__ float g_ps[4][N_ROWS];   // per-j-quarter exp-sum partials
__device__ float g_posd[N_ROWS];
__device__ float g_part[32];

// ---------------- arch-neutral PTX helpers (sm_90 baseline) ----------------
__device__ __forceinline__ uint32_t smem_u32(const void* p) {
    uint32_t a;
    asm("{ .reg .u64 t; cvta.to.shared.u64 t, %1; cvt.u32.u64 %0, t; }" : "=r"(a) : "l"(p));
    return a;
}
#define MBARRIER_INIT(addr, cnt) \
    asm volatile("mbarrier.init.shared.b64 [%0], %1;" :: "r"(addr), "r"((uint32_t)(cnt)) : "memory")
#define MBARRIER_EXPECT_TX(addr, bytes) \
    asm volatile("mbarrier.arrive.expect_tx.shared.b64 _, [%0], %1;" :: "r"(addr), "r"((uint32_t)(bytes)) : "memory")
#define MBARRIER_ARRIVE(addr) \
    asm volatile("mbarrier.arrive.shared.b64 _, [%0];" :: "r"(addr) : "memory")
#define MBARRIER_WAIT_PARITY(addr, par) do {                                   \
    uint32_t _m = (addr), _p = (uint32_t)(par), _done;                          \
    asm volatile("{\n\t.reg .pred p;\n\t"                                       \
        "mbarrier.try_wait.parity.acquire.cta.shared::cta.b64 p, [%1], %2;\n\t" \
        "selp.b32 %0, 1, 0, p;\n\t}" : "=r"(_done) : "r"(_m), "r"(_p) : "memory"); \
    if (!_done) {                                                               \
        asm volatile("{\n\t.reg .pred P1;\n\t"                                  \
            "WL_%=:\n\t"                                                        \
            "mbarrier.try_wait.parity.acquire.cta.shared::cta.b64 P1, [%0], %1, 0x989680;\n\t" \
            "@P1 bra.uni WD_%=;\n\t"                                            \
            "bra.uni WL_%=;\n\t"                                                \
            "WD_%=:\n\t}" :: "r"(_m), "r"(_p) : "memory");                      \
    } } while (0)

__device__ __forceinline__ void bulk_copy(uint32_t dst_smem, const void* src, uint32_t bytes, uint32_t mbar) {
    asm volatile("cp.async.bulk.shared::cluster.global.mbarrier::complete_tx::bytes [%0], [%1], %2, [%3];"
        :: "r"(dst_smem), "l"(src), "r"(bytes), "r"(mbar) : "memory");
}
__device__ __forceinline__ float fast_ex2(float x) {
    float y; asm("ex2.approx.f32 %0, %1;" : "=f"(y) : "f"(x)); return y;
}
__device__ __forceinline__ uint32_t swz128(uint32_t x) { return x ^ ((x >> 3) & 0x70); }

// ---------------- tcgen05 helpers (sm_103a only) ----------------
#if TC_ENABLED
#define TCGEN05_ALLOC(sm, n) \
    asm volatile("tcgen05.alloc.cta_group::1.sync.aligned.shared::cta.b32 [%0], %1;" :: "r"(sm), "r"((uint32_t)(n)) : "memory")
#define TCGEN05_DEALLOC(t, n) \
    asm volatile("tcgen05.dealloc.cta_group::1.sync.aligned.b32 %0, %1;" :: "r"(t), "r"((uint32_t)(n)))
#define TCGEN05_RELINQ() \
    asm volatile("tcgen05.relinquish_alloc_permit.cta_group::1.sync.aligned;")
#define TCGEN05_COMMIT(mb) \
    asm volatile("tcgen05.commit.cta_group::1.mbarrier::arrive::one.shared::cluster.b64 [%0];" :: "r"(mb) : "memory")
#define TCGEN05_WAIT_LD()  asm volatile("tcgen05.wait::ld.sync.aligned;" ::: "memory")
#define TCGEN05_FENCE_BEFORE() asm volatile("tcgen05.fence::before_thread_sync;" ::: "memory")
#define TCGEN05_FENCE_AFTER()  asm volatile("tcgen05.fence::after_thread_sync;" ::: "memory")

#define TCGEN05_LD_X16(r, a) \
    asm volatile("tcgen05.ld.sync.aligned.32x32b.x16.b32 " \
        "{%0,%1,%2,%3,%4,%5,%6,%7,%8,%9,%10,%11,%12,%13,%14,%15}, [%16];" \
        : "=r"((r)[0]),"=r"((r)[1]),"=r"((r)[2]),"=r"((r)[3]),"=r"((r)[4]),"=r"((r)[5]),"=r"((r)[6]),"=r"((r)[7]), \
          "=r"((r)[8]),"=r"((r)[9]),"=r"((r)[10]),"=r"((r)[11]),"=r"((r)[12]),"=r"((r)[13]),"=r"((r)[14]),"=r"((r)[15]) \
        : "r"(a))

// SW128 descriptor: layout=2 (SW128), version=1, SBO=64, LBO=1
__device__ __forceinline__ uint64_t make_desc(uint32_t addr) {
    uint64_t base = (uint64_t(2) << 61) | (uint64_t(1) << 46) | (uint64_t(64) << 32) | (uint64_t(1) << 16);
    return base | ((uint64_t)(addr >> 4) & 0x3FFF);
}
__device__ __forceinline__ void mma_f16_ss(uint32_t d, uint64_t ad, uint64_t bd, uint32_t idesc, bool en) {
    uint32_t e = en ? 1u : 0u;
    asm volatile("{\n\t.reg .pred p;\n\tsetp.ne.u32 p, %5, 0;\n\t"
        "tcgen05.mma.cta_group::1.kind::f16 [%0], %1, %2, %3, {%4,%4,%4,%4}, p;\n\t}"
        :: "r"(d), "l"(ad), "l"(bd), "r"(idesc), "r"(0u), "r"(e) : "memory");
}

// Issue the 16 MMAs for half-of-tile H (K-half hk over both A tiles), tid 0 only.
__device__ __forceinline__ void issue_half(int H, uint32_t smem_base, uint32_t tmem_base) {
    const int slot = H % 3, rnd = H / 3;
    const int l = H >> 1, hk = H & 1, p = l & 1;
    MBARRIER_WAIT_PARITY(BAR(1 + slot), rnd & 1);          // B half delivered
    if (hk == 0 && l >= 2)
        MBARRIER_WAIT_PARITY(BAR(7 + p), ((l >> 1) - 1) & 1); // D pair free
    TCGEN05_FENCE_AFTER();
    const uint32_t bbase = smem_base + SMEM_B + slot * HALF_BYTES;
    #pragma unroll
    for (int a = 0; a < 2; ++a) {
        const uint32_t abase = smem_base + SMEM_A + a * TILE_BYTES + hk * HALF_BYTES;
        const uint32_t dt = tmem_base + (p * 2 + a) * 128;
        #pragma unroll
        for (int kcl = 0; kcl < 2; ++kcl)
            #pragma unroll
            for (int q = 0; q < 4; ++q)
                mma_f16_ss(dt,
                           make_desc(abase + kcl * SUBK_BYTES) + q * 2,
                           make_desc(bbase + kcl * SUBK_BYTES) + q * 2,
                           IDESC_F16, !(hk == 0 && kcl == 0 && q == 0));
    }
    TCGEN05_COMMIT(BAR(4 + slot));
}

// TMA one B half-tile into ring slot, tid 32 only.
__device__ __forceinline__ void produce_half(int H, int q, uint32_t smem_base) {
    const int slot = H % 3, rnd = H / 3;
    if (rnd >= 1) MBARRIER_WAIT_PARITY(BAR(4 + slot), (rnd - 1) & 1); // MMA done with slot
    MBARRIER_EXPECT_TX(BAR(1 + slot), HALF_BYTES);
    bulk_copy(smem_base + SMEM_B + slot * HALF_BYTES,
              g_zswz + (size_t)(q * 16 + (H >> 1)) * TILE_BYTES + (size_t)(H & 1) * HALF_BYTES,
              HALF_BYTES, BAR(1 + slot));
}

// process 16 TMEM values: e = exp2(2*log2e*(d-1)); accumulate
// MODE: 0 = plain, 1 = diagonal tile (mask j==i), 2 = positive tile (capture d)
template<int MODE>
__device__ __forceinline__ void proc16(const uint32_t* dv, int cb, int rrow, int gi,
                                       float& a0, float& a1, float& a2, float& a3) {
    const float C1 = 2.8853900817779268f;   // 2*log2(e)
    #pragma unroll
    for (int k = 0; k < 16; ++k) {
        float d = __uint_as_float(dv[k]);
        float e = fast_ex2(fmaf(d, C1, -C1));
        if (MODE == 1) { if (cb + k == rrow) e = 0.f; }
        if (MODE == 2) { if (cb + k == rrow) g_posd[gi] = d; }
        if ((k & 3) == 0) a0 += e; else if ((k & 3) == 1) a1 += e;
        else if ((k & 3) == 2) a2 += e; else a3 += e;
    }
}

// pipelined 128x64 region epilogue; optionally frees the D pair at the end
template<int MODE, bool ARRIVE>
__device__ __forceinline__ void epi_region(uint32_t taddr, int colbase, int rrow, int gi,
                                           uint32_t dfree_bar, int lane,
                                           float& a0, float& a1, float& a2, float& a3) {
    uint32_t dvA[16], dvB[16];
    TCGEN05_LD_X16(dvA, taddr + 0);
    TCGEN05_WAIT_LD();
    TCGEN05_LD_X16(dvB, taddr + 16);
    proc16<MODE>(dvA, colbase + 0, rrow, gi, a0, a1, a2, a3);
    TCGEN05_WAIT_LD();
    TCGEN05_LD_X16(dvA, taddr + 32);
    proc16<MODE>(dvB, colbase + 16, rrow, gi, a0, a1, a2, a3);
    TCGEN05_WAIT_LD();
    TCGEN05_LD_X16(dvB, taddr + 48);
    proc16<MODE>(dvA, colbase + 32, rrow, gi, a0, a1, a2, a3);
    TCGEN05_WAIT_LD();
    if (ARRIVE) {
        TCGEN05_FENCE_BEFORE();
        if (lane == 0) MBARRIER_ARRIVE(dfree_bar);
    }
    proc16<MODE>(dvB, colbase + 48, rrow, gi, a0, a1, a2, a3);
}

template<bool ARRIVE>
__device__ __forceinline__ void epi_dispatch(int mode, uint32_t taddr, int colbase, int rrow, int gi,
                                             uint32_t dfree_bar, int lane,
                                             float& a0, float& a1, float& a2, float& a3) {
    if (mode == 1)      epi_region<1, ARRIVE>(taddr, colbase, rrow, gi, dfree_bar, lane, a0, a1, a2, a3);
    else if (mode == 2) epi_region<2, ARRIVE>(taddr, colbase, rrow, gi, dfree_bar, lane, a0, a1, a2, a3);
    else                epi_region<0, ARRIVE>(taddr, colbase, rrow, gi, dfree_bar, lane, a0, a1, a2, a3);
}
#endif // TC_ENABLED

// ---------------------------------------------------------------------------
// Kernel 1: normalize rows, convert to bf16, store PRE-SWIZZLED tile layout.
// ---------------------------------------------------------------------------
__global__ void prep_kernel(const float* __restrict__ zi, const float* __restrict__ zj) {
    int warp = (blockIdx.x * blockDim.x + threadIdx.x) >> 5;
    int lane = threadIdx.x & 31;
    if (warp >= N_ROWS) return;
    const float* src = (warp < B_ROWS) ? (zi + (size_t)warp * D_DIM)
                                       : (zj + (size_t)(warp - B_ROWS) * D_DIM);
    const float4* s4 = (const float4*)src;
    float4 v0 = s4[lane * 2];
    float4 v1 = s4[lane * 2 + 1];
    float ss = v0.x*v0.x + v0.y*v0.y + v0.z*v0.z + v0.w*v0.w
             + v1.x*v1.x + v1.y*v1.y + v1.z*v1.z + v1.w*v1.w;
    #pragma unroll
    for (int o = 16; o; o >>= 1) ss += __shfl_xor_sync(0xffffffffu, ss, o);
    float inv = 1.0f / fmaxf(sqrtf(ss), 1e-12f);

    __nv_bfloat162 p0 = __floats2bfloat162_rn(v0.x*inv, v0.y*inv);
    __nv_bfloat162 p1 = __floats2bfloat162_rn(v0.z*inv, v0.w*inv);
    __nv_bfloat162 p2 = __floats2bfloat162_rn(v1.x*inv, v1.y*inv);
    __nv_bfloat162 p3 = __floats2bfloat162_rn(v1.z*inv, v1.w*inv);
    uint4 u;
    u.x = *reinterpret_cast<uint32_t*>(&p0);
    u.y = *reinterpret_cast<uint32_t*>(&p1);
    u.z = *reinterpret_cast<uint32_t*>(&p2);
    u.w = *reinterpret_cast<uint32_t*>(&p3);

    int t = warp >> 7, r = warp & 127;
    int kc = lane >> 3;                         // which K 64-chunk
    uint32_t inner = swz128((uint32_t)(r * 128 + (lane & 7) * 16));
    *reinterpret_cast<uint4*>(g_zswz + (size_t)t * TILE_BYTES + kc * SUBK_BYTES + inner) = u;
}

// ---------------------------------------------------------------------------
// Kernel 2: tcgen05 GEMM, M=256 resident per CTA, j-quarter per CTA.
// Grid 128: mm = bid & 31 (rows 256*mm..), q = bid >> 5 (j tiles q*16..q*16+15).
// ---------------------------------------------------------------------------
__global__ __launch_bounds__(256, 1) void gemm_lse_kernel() {
#if TC_ENABLED
    extern __shared__ char smem[];
    const uint32_t smem_base = smem_u32(smem);
    const int tid  = threadIdx.x;
    const int wid  = tid >> 5;
    const int lane = tid & 31;
    const int mm   = blockIdx.x & 31;
    const int q    = blockIdx.x >> 5;
    const int NT   = 16;                        // j tiles per CTA

    if (wid == 0) TCGEN05_ALLOC(smem_base + SMEM_CTRL, 512);
    if (tid == 0) {
        MBARRIER_INIT(BAR(0), 1);                                   // a_full
        MBARRIER_INIT(BAR(1), 1); MBARRIER_INIT(BAR(2), 1); MBARRIER_INIT(BAR(3), 1); // b_full
        MBARRIER_INIT(BAR(4), 1); MBARRIER_INIT(BAR(5), 1); MBARRIER_INIT(BAR(6), 1); // hdone
        MBARRIER_INIT(BAR(7), 8); MBARRIER_INIT(BAR(8), 8);         // d_free (8 warps)
    }
    __syncthreads();
    uint32_t tmem_base;
    asm volatile("ld.shared.b32 %0, [%1];" : "=r"(tmem_base) : "r"(smem_base + SMEM_CTRL));

    // --- prologue ---
    if (tid == 32) {
        MBARRIER_EXPECT_TX(BAR(0), 2 * TILE_BYTES);
        bulk_copy(smem_base + SMEM_A, g_zswz + (size_t)(2 * mm) * TILE_BYTES, 2 * TILE_BYTES, BAR(0));
        produce_half(0, q, smem_base);
        produce_half(1, q, smem_base);
        produce_half(2, q, smem_base);
        produce_half(3, q, smem_base);          // waits hdone[0] (tid0's half 0)
    }
    if (tid == 0) {
        MBARRIER_WAIT_PARITY(BAR(0), 0);        // A resident
        issue_half(0, smem_base, tmem_base);
        issue_half(1, smem_base, tmem_base);
    }

    // --- epilogue state ---
    const int rrow    = (wid & 3) * 32 + lane;
    const int colbase = (tid >> 7) * 64;
    const int gbase   = mm * 256;
    float acc[2][4] = {{0.f,0.f,0.f,0.f},{0.f,0.f,0.f,0.f}};

    for (int l = 0; l < NT; ++l) {
        const int p = l & 1;
        const int jt = q * 16 + l;

        // keep tensor + TMA pipelines fed BEFORE blocking on tile l's result
        if (tid == 0 && l + 1 < NT) {
            issue_half(2 * l + 2, smem_base, tmem_base);
            issue_half(2 * l + 3, smem_base, tmem_base);
        }
        if (tid == 32) {
            if (2 * l + 4 < 2 * NT) produce_half(2 * l + 4, q, smem_base);
            if (2 * l + 5 < 2 * NT) produce_half(2 * l + 5, q, smem_base);
        }

        // wait for tile l's MMAs (hdone of its second half)
        const int H2 = 2 * l + 1;
        MBARRIER_WAIT_PARITY(BAR(4 + H2 % 3), (H2 / 3) & 1);
        TCGEN05_FENCE_AFTER();

        // two 128-row regions (A0: a=0, A1: a=1)
        #pragma unroll
        for (int a = 0; a < 2; ++a) {
            const int tA   = 2 * mm + a;
            const int mode = (jt == tA) ? 1 : ((jt == (tA ^ 32)) ? 2 : 0);
            const int gi   = gbase + a * 128 + rrow;
            const uint32_t taddr = tmem_base + (p * 2 + a) * 128 + colbase
                                 + ((uint32_t)((tid & 127) >> 5) << 21);
            if (a == 0)
                epi_dispatch<false>(mode, taddr, colbase, rrow, gi, 0, lane,
                                    acc[0][0], acc[0][1], acc[0][2], acc[0][3]);
            else
                epi_dispatch<true>(mode, taddr, colbase, rrow, gi, BAR(7 + p), lane,
                                   acc[1][0], acc[1][1], acc[1][2], acc[1][3]);
        }
    }

    // --- combine column-half partials per row, store ---
    float* sred = reinterpret_cast<float*>(smem + SMEM_SRED);
    const int wg = tid >> 7;
    sred[wg * 256 + 0   + rrow] = (acc[0][0] + acc[0][1]) + (acc[0][2] + acc[0][3]);
    sred[wg * 256 + 128 + rrow] = (acc[1][0] + acc[1][1]) + (acc[1][2] + acc[1][3]);
    __syncthreads();
    if (tid < 256) g_ps[q][gbase + tid] = sred[tid] + sred[256 + tid];

    __syncthreads();
    if (wid == 0) { TCGEN05_RELINQ(); TCGEN05_DEALLOC(tmem_base, 512); }
#endif // TC_ENABLED
}

// ---------------------------------------------------------------------------
// Kernel 3a: per-row loss (parallel logf), block partials. Grid 32 x 256.
// ---------------------------------------------------------------------------
__global__ void row_loss_kernel() {
    __shared__ float sb[256];
    const int tid = threadIdx.x;
    const int i = blockIdx.x * 256 + tid;
    float S = (g_ps[0][i] + g_ps[1][i]) + (g_ps[2][i] + g_ps[3][i]);
    sb[tid] = 2.0f + logf(S) - 2.0f * g_posd[i];
    __syncthreads();
    #pragma unroll
    for (int o = 128; o; o >>= 1) {
        if (tid < o) sb[tid] += sb[tid + o];
        __syncthreads();
    }
    if (tid == 0) g_part[blockIdx.x] = sb[0];
}

// ---------------------------------------------------------------------------
// Kernel 3b: final 32-value sum + mean.
// ---------------------------------------------------------------------------
__global__ void final_kernel(float* __restrict__ out) {
    const int lane = threadIdx.x;
    float v = g_part[lane];
    #pragma unroll
    for (int o = 16; o; o >>= 1) v += __shfl_xor_sync(0xffffffffu, v, o);
    if (lane == 0) out[0] = v / (float)N_ROWS;
}

// ---------------------------------------------------------------------------
extern "C" void kernel_launch(void* const* d_in, const int* in_sizes, int n_in,
                              void* d_out, int out_size) {
    const float* zi = (const float*)d_in[0];
    const float* zj = (const float*)d_in[1];
    float* out = (float*)d_out;

    cudaFuncSetAttribute(gemm_lse_kernel,
                         cudaFuncAttributeMaxDynamicSharedMemorySize, SMEM_TOTAL);

    prep_kernel<<<(N_ROWS * 32) / 256, 256>>>(zi, zj);
    gemm_lse_kernel<<<128, 256, SMEM_TOTAL>>>();
    row_loss_kernel<<<32, 256>>>();
    final_kernel<<<1, 32>>>(out);
}